// round 3
// baseline (speedup 1.0000x reference)
#include <cuda_runtime.h>
#include <math.h>
#include <stdint.h>

#define N_NODES 50000
#define E_EDGES 800000
#define NFEAT   512
#define NHID    256
#define NCLASS  64

// Scratch (static __device__ arrays; no allocations allowed in kernel_launch)
__device__ float g_xw1[N_NODES * NHID];   // x @ W1
__device__ float g_h  [N_NODES * NHID];   // spmm0 accumulator (pre-relu)
__device__ float g_hw2[N_NODES * NCLASS]; // relu(h+b1) @ W2
__device__ float g_h2 [N_NODES * NCLASS]; // spmm1 accumulator

// ---------------------------------------------------------------------------
// Zero both accumulators
// ---------------------------------------------------------------------------
__global__ void zero_kernel() {
    int i = blockIdx.x * blockDim.x + threadIdx.x;
    const int t1 = N_NODES * NHID / 4;
    const int t2 = N_NODES * NCLASS / 4;
    float4 z = make_float4(0.f, 0.f, 0.f, 0.f);
    if (i < t1) ((float4*)g_h)[i] = z;
    if (i < t2) ((float4*)g_h2)[i] = z;
}

// ---------------------------------------------------------------------------
// TF32 helpers
// ---------------------------------------------------------------------------
__device__ __forceinline__ uint32_t f2tf32(float f) {
    uint32_t r;
    asm("cvt.rna.tf32.f32 %0, %1;" : "=r"(r) : "f"(f));
    return r;
}

// split fp32 value into (hi, lo) tf32 bit patterns, packed as float2
__device__ __forceinline__ float2 split_tf32(float a) {
    uint32_t hb = f2tf32(a);
    float hf = __uint_as_float(hb);
    uint32_t lb = f2tf32(a - hf);
    return make_float2(__uint_as_float(hb), __uint_as_float(lb));
}

__device__ __forceinline__ void mma_tf32(float c[4],
    uint32_t a0, uint32_t a1, uint32_t a2, uint32_t a3,
    uint32_t b0, uint32_t b1)
{
    asm volatile(
        "mma.sync.aligned.m16n8k8.row.col.f32.tf32.tf32.f32 "
        "{%0,%1,%2,%3}, {%4,%5,%6,%7}, {%8,%9}, {%0,%1,%2,%3};"
        : "+f"(c[0]), "+f"(c[1]), "+f"(c[2]), "+f"(c[3])
        : "r"(a0), "r"(a1), "r"(a2), "r"(a3), "r"(b0), "r"(b1));
}

// ---------------------------------------------------------------------------
// Tensor-core GEMM, 3xTF32 split. C(MxNc) = op(A)(MxK) @ B(KxNc).
// Block tile 128 x BTN, K-step 16, 8 warps, warp tile 32 x (BTN/2).
// FUSE: A element -> relu(a + bias[k]) before use (for GEMM2).
// ---------------------------------------------------------------------------
template<int BTN, bool FUSE>
__global__ __launch_bounds__(256) void tmma_gemm(
    const float* __restrict__ A, const float* __restrict__ bias,
    const float* __restrict__ B, float* __restrict__ C,
    int M, int Nc, int K)
{
    constexpr int PA = 17;        // As row pitch in float2
    constexpr int PB = BTN + 2;   // Bs row pitch in float2
    __shared__ float2 As[128 * PA];   // [row][k]  hi/lo packed
    __shared__ float2 Bs[16 * PB];    // [k][n]    hi/lo packed

    const int tid  = threadIdx.x;
    const int warp = tid >> 5;
    const int lane = tid & 31;
    const int warpM = warp & 3;       // 0..3
    const int warpN = warp >> 2;      // 0..1
    constexpr int WN = BTN / 2;       // warp n-extent
    constexpr int NT = WN / 8;        // n8 tiles per warp
    const int m0 = warpM * 32;
    const int n0 = warpN * WN;
    const int rowBlock = blockIdx.y * 128;
    const int colBlock = blockIdx.x * BTN;

    const int l4 = lane >> 2;         // 0..7
    const int lm = lane & 3;          // 0..3

    float acc[2][NT][4];
    #pragma unroll
    for (int mt = 0; mt < 2; mt++)
        #pragma unroll
        for (int nt = 0; nt < NT; nt++)
            #pragma unroll
            for (int j = 0; j < 4; j++) acc[mt][nt][j] = 0.f;

    for (int k0 = 0; k0 < K; k0 += 16) {
        // ---- load A tile: 128 x 16 fp32, split to hi/lo ----
        #pragma unroll
        for (int i = tid; i < 128 * 4; i += 256) {  // 512 float4
            int r  = i >> 2;
            int c4 = (i & 3) << 2;
            int gr = rowBlock + r;
            float4 av;
            if (gr < M) {
                av = *(const float4*)(A + (size_t)gr * K + k0 + c4);
                if (FUSE) {
                    float4 bb = *(const float4*)(bias + k0 + c4);
                    av.x = fmaxf(av.x + bb.x, 0.f);
                    av.y = fmaxf(av.y + bb.y, 0.f);
                    av.z = fmaxf(av.z + bb.z, 0.f);
                    av.w = fmaxf(av.w + bb.w, 0.f);
                }
            } else {
                av = make_float4(0.f, 0.f, 0.f, 0.f);
            }
            float2* dst = &As[r * PA + c4];
            dst[0] = split_tf32(av.x);
            dst[1] = split_tf32(av.y);
            dst[2] = split_tf32(av.z);
            dst[3] = split_tf32(av.w);
        }
        // ---- load B tile: 16 x BTN fp32, split to hi/lo ----
        #pragma unroll
        for (int i = tid; i < 16 * (BTN / 4); i += 256) {
            int kr = i / (BTN / 4);
            int nc = (i % (BTN / 4)) << 2;
            float4 bv = *(const float4*)(B + (size_t)(k0 + kr) * Nc + colBlock + nc);
            float2* dst = &Bs[kr * PB + nc];
            dst[0] = split_tf32(bv.x);
            dst[1] = split_tf32(bv.y);
            dst[2] = split_tf32(bv.z);
            dst[3] = split_tf32(bv.w);
        }
        __syncthreads();

        // ---- two k8 steps ----
        #pragma unroll
        for (int kk = 0; kk < 16; kk += 8) {
            uint32_t ah[2][4], al[2][4];
            #pragma unroll
            for (int mt = 0; mt < 2; mt++) {
                const float2* ap = &As[(m0 + mt * 16 + l4) * PA + kk + lm];
                float2 a0 = ap[0];
                float2 a1 = ap[8 * PA];
                float2 a2 = ap[4];
                float2 a3 = ap[8 * PA + 4];
                ah[mt][0] = __float_as_uint(a0.x); al[mt][0] = __float_as_uint(a0.y);
                ah[mt][1] = __float_as_uint(a1.x); al[mt][1] = __float_as_uint(a1.y);
                ah[mt][2] = __float_as_uint(a2.x); al[mt][2] = __float_as_uint(a2.y);
                ah[mt][3] = __float_as_uint(a3.x); al[mt][3] = __float_as_uint(a3.y);
            }
            #pragma unroll
            for (int nt = 0; nt < NT; nt++) {
                const float2* bp = &Bs[(kk + lm) * PB + n0 + nt * 8 + l4];
                float2 b0 = bp[0];
                float2 b1 = bp[4 * PB];
                uint32_t bh0 = __float_as_uint(b0.x), bl0 = __float_as_uint(b0.y);
                uint32_t bh1 = __float_as_uint(b1.x), bl1 = __float_as_uint(b1.y);
                #pragma unroll
                for (int mt = 0; mt < 2; mt++) {
                    mma_tf32(acc[mt][nt], ah[mt][0], ah[mt][1], ah[mt][2], ah[mt][3], bh0, bh1);
                    mma_tf32(acc[mt][nt], ah[mt][0], ah[mt][1], ah[mt][2], ah[mt][3], bl0, bl1);
                    mma_tf32(acc[mt][nt], al[mt][0], al[mt][1], al[mt][2], al[mt][3], bh0, bh1);
                }
            }
        }
        __syncthreads();
    }

    // ---- epilogue ----
    #pragma unroll
    for (int mt = 0; mt < 2; mt++) {
        int r = rowBlock + m0 + mt * 16 + l4;
        #pragma unroll
        for (int nt = 0; nt < NT; nt++) {
            int c = colBlock + n0 + nt * 8 + lm * 2;
            if (r < M)
                *(float2*)(C + (size_t)r * Nc + c) =
                    make_float2(acc[mt][nt][0], acc[mt][nt][1]);
            if (r + 8 < M)
                *(float2*)(C + (size_t)(r + 8) * Nc + c) =
                    make_float2(acc[mt][nt][2], acc[mt][nt][3]);
        }
    }
}

// ---------------------------------------------------------------------------
// SPMM over NHID=256 features: warp per edge, red.global.add.v4.f32 scatter
// ---------------------------------------------------------------------------
__device__ __forceinline__ void red_add_v4(float4* ptr, float4 v) {
    asm volatile("red.global.add.v4.f32 [%0], {%1,%2,%3,%4};"
                 :: "l"(ptr), "f"(v.x), "f"(v.y), "f"(v.z), "f"(v.w)
                 : "memory");
}

__global__ __launch_bounds__(256) void spmm_nhid(
    const int* __restrict__ row, const int* __restrict__ col,
    const float* __restrict__ val)
{
    int e = blockIdx.x * (blockDim.x >> 5) + (threadIdx.x >> 5);
    if (e >= E_EDGES) return;
    int lane = threadIdx.x & 31;
    int c = col[e];
    int r = row[e];
    float v = val[e];
    const float4* s = (const float4*)(g_xw1 + (long)c * NHID);
    float4*       d = (float4*)(g_h   + (long)r * NHID);
    #pragma unroll
    for (int j = 0; j < 2; j++) {
        float4 x = s[lane + 32 * j];
        x.x *= v; x.y *= v; x.z *= v; x.w *= v;
        red_add_v4(d + lane + 32 * j, x);
    }
}

// ---------------------------------------------------------------------------
// SPMM over NCLASS=64 features: 16 threads per edge
// ---------------------------------------------------------------------------
__global__ __launch_bounds__(256) void spmm_ncls(
    const int* __restrict__ row, const int* __restrict__ col,
    const float* __restrict__ val)
{
    long t = (long)blockIdx.x * blockDim.x + threadIdx.x;
    int e = (int)(t >> 4);
    if (e >= E_EDGES) return;
    int l = (int)(t & 15);
    int c = col[e];
    int r = row[e];
    float v = val[e];
    const float4* s = (const float4*)(g_hw2 + (long)c * NCLASS);
    float4*       d = (float4*)(g_h2  + (long)r * NCLASS);
    float4 x = s[l];
    x.x *= v; x.y *= v; x.z *= v; x.w *= v;
    red_add_v4(d + l, x);
}

// ---------------------------------------------------------------------------
// Final: logits = (h2 + b2) @ LW + Lb ; log_softmax. One warp per node.
// ---------------------------------------------------------------------------
__global__ __launch_bounds__(256) void final_kernel(
    const float* __restrict__ b2, const float* __restrict__ LW,
    const float* __restrict__ Lb, float* __restrict__ out)
{
    __shared__ float sLW[NCLASS * NCLASS];  // [k][c], 16KB
    __shared__ float sh2[8][NCLASS];
    const int tid = threadIdx.x;
    for (int i = tid; i < NCLASS * NCLASS; i += 256) sLW[i] = LW[i];

    const int warp = tid >> 5;
    const int lane = tid & 31;
    const int node = blockIdx.x * 8 + warp;

    if (node < N_NODES) {
        sh2[warp][lane]      = g_h2[(long)node * NCLASS + lane]      + b2[lane];
        sh2[warp][lane + 32] = g_h2[(long)node * NCLASS + lane + 32] + b2[lane + 32];
    }
    __syncthreads();
    if (node >= N_NODES) return;

    float l0 = Lb[lane];
    float l1 = Lb[lane + 32];
    #pragma unroll
    for (int k = 0; k < NCLASS; k++) {
        float hv = sh2[warp][k];
        l0 += hv * sLW[k * NCLASS + lane];
        l1 += hv * sLW[k * NCLASS + lane + 32];
    }

    float m = fmaxf(l0, l1);
    #pragma unroll
    for (int off = 16; off; off >>= 1)
        m = fmaxf(m, __shfl_xor_sync(0xffffffff, m, off));
    float s = expf(l0 - m) + expf(l1 - m);
    #pragma unroll
    for (int off = 16; off; off >>= 1)
        s += __shfl_xor_sync(0xffffffff, s, off);
    float lse = m + logf(s);

    out[(long)node * NCLASS + lane]      = l0 - lse;
    out[(long)node * NCLASS + lane + 32] = l1 - lse;
}

// ---------------------------------------------------------------------------
// Launch
// ---------------------------------------------------------------------------
extern "C" void kernel_launch(void* const* d_in, const int* in_sizes, int n_in,
                              void* d_out, int out_size)
{
    const float* x   = (const float*)d_in[0];
    const float* a0v = (const float*)d_in[1];
    const float* a1v = (const float*)d_in[2];
    const float* W1  = (const float*)d_in[3];
    const float* b1  = (const float*)d_in[4];
    const float* W2  = (const float*)d_in[5];
    const float* b2  = (const float*)d_in[6];
    const float* LW  = (const float*)d_in[7];
    const float* Lb  = (const float*)d_in[8];
    const int*   a0r = (const int*)d_in[9];
    const int*   a0c = (const int*)d_in[10];
    const int*   a1r = (const int*)d_in[11];
    const int*   a1c = (const int*)d_in[12];
    float* out = (float*)d_out;

    float *p_xw1, *p_h, *p_hw2;
    cudaGetSymbolAddress((void**)&p_xw1, g_xw1);
    cudaGetSymbolAddress((void**)&p_h,   g_h);
    cudaGetSymbolAddress((void**)&p_hw2, g_hw2);

    // Zero accumulators (covers both g_h and g_h2)
    {
        int threads = N_NODES * NHID / 4;
        zero_kernel<<<(threads + 255) / 256, 256>>>();
    }

    // GEMM1 (tensor, 3xTF32): g_xw1 = x @ W1  (50000x512 * 512x256)
    {
        dim3 grid(NHID / 128, (N_NODES + 127) / 128);
        tmma_gemm<128, false><<<grid, 256>>>(x, nullptr, W1, p_xw1,
                                             N_NODES, NHID, NFEAT);
    }

    // SPMM0: g_h += adj0 * g_xw1   (warp per edge)
    {
        int blocks = (E_EDGES + 7) / 8;
        spmm_nhid<<<blocks, 256>>>(a0r, a0c, a0v);
    }

    // GEMM2 (tensor, 3xTF32, fused relu+b1 on A): g_hw2 = relu(g_h+b1) @ W2
    {
        dim3 grid(1, (N_NODES + 127) / 128);
        tmma_gemm<64, true><<<grid, 256>>>(p_h, b1, W2, p_hw2,
                                           N_NODES, NCLASS, NHID);
    }

    // SPMM1: g_h2 += adj1 * g_hw2   (16 threads per edge)
    {
        long threads = (long)E_EDGES * 16;
        spmm_ncls<<<(int)((threads + 255) / 256), 256>>>(a1r, a1c, a1v);
    }

    // Final linear + log_softmax
    {
        final_kernel<<<(N_NODES + 7) / 8, 256>>>(b2, LW, Lb, out);
    }
}

// round 5
// speedup vs baseline: 1.3869x; 1.3869x over previous
#include <cuda_runtime.h>
#include <cuda_bf16.h>
#include <math.h>
#include <stdint.h>

#define N_NODES 50000
#define M_PAD   50048          // 391 * 128
#define E_EDGES 800000
#define NFEAT   512
#define NHID    256
#define NCLASS  64

// fp32 scratch
__device__ float g_xw1[N_NODES * NHID];   // x @ W1
__device__ float g_h  [N_NODES * NHID];   // spmm0 accumulator (pre-relu)
__device__ float g_hw2[N_NODES * NCLASS]; // relu(h+b1) @ W2
__device__ float g_h2 [N_NODES * NCLASS]; // spmm1 accumulator

// bf16 split operands:  A' = [Ah | Al | Ah],  B't = [Bh | Bh | Bl] (n-major rows)
__device__ __nv_bfloat16 g_A1[(size_t)M_PAD * (3 * NFEAT)];
__device__ __nv_bfloat16 g_B1[(size_t)NHID  * (3 * NFEAT)];
__device__ __nv_bfloat16 g_A2[(size_t)M_PAD * (3 * NHID)];
__device__ __nv_bfloat16 g_B2[(size_t)NCLASS * (3 * NHID)];

// ---------------------------------------------------------------------------
// Zero accumulators
// ---------------------------------------------------------------------------
__global__ void zero_kernel() {
    int i = blockIdx.x * blockDim.x + threadIdx.x;
    const int t1 = N_NODES * NHID / 4;
    const int t2 = N_NODES * NCLASS / 4;
    float4 z = make_float4(0.f, 0.f, 0.f, 0.f);
    if (i < t1) ((float4*)g_h)[i] = z;
    if (i < t2) ((float4*)g_h2)[i] = z;
}

// ---------------------------------------------------------------------------
// Split fp32 matrix -> bf16 [Ah | Al | Ah], optional fused relu(x + bias)
// ---------------------------------------------------------------------------
template<bool RELU>
__global__ __launch_bounds__(256) void conv_split(
    const float* __restrict__ src, const float* __restrict__ bias,
    __nv_bfloat16* __restrict__ dst, int Msrc, int K)
{
    long idx = (long)blockIdx.x * blockDim.x + threadIdx.x;
    long total = (long)M_PAD * (K / 4);
    if (idx >= total) return;
    int r  = (int)(idx / (K / 4));
    int k4 = (int)(idx % (K / 4)) * 4;

    float4 v = make_float4(0.f, 0.f, 0.f, 0.f);
    if (r < Msrc) {
        v = *(const float4*)(src + (size_t)r * K + k4);
        if (RELU) {
            float4 bb = *(const float4*)(bias + k4);
            v.x = fmaxf(v.x + bb.x, 0.f);
            v.y = fmaxf(v.y + bb.y, 0.f);
            v.z = fmaxf(v.z + bb.z, 0.f);
            v.w = fmaxf(v.w + bb.w, 0.f);
        }
    }
    float a[4] = {v.x, v.y, v.z, v.w};
    unsigned long long ph = 0, pl = 0;
    #pragma unroll
    for (int i = 0; i < 4; i++) {
        __nv_bfloat16 h = __float2bfloat16(a[i]);
        __nv_bfloat16 l = __float2bfloat16(a[i] - __bfloat162float(h));
        ph |= (unsigned long long)__bfloat16_as_ushort(h) << (16 * i);
        pl |= (unsigned long long)__bfloat16_as_ushort(l) << (16 * i);
    }
    __nv_bfloat16* row = dst + (size_t)r * 3 * K;
    *(unsigned long long*)(row + k4)         = ph;
    *(unsigned long long*)(row + K + k4)     = pl;
    *(unsigned long long*)(row + 2 * K + k4) = ph;
}

// ---------------------------------------------------------------------------
// Split weight W[K][N] (row-major) -> Bt[N][3K] bf16 = [Bh | Bh | Bl]
// ---------------------------------------------------------------------------
__global__ __launch_bounds__(256) void conv_w(
    const float* __restrict__ W, __nv_bfloat16* __restrict__ Bt, int K, int N)
{
    int idx = blockIdx.x * blockDim.x + threadIdx.x;
    if (idx >= K * N) return;
    int n = idx / K, k = idx % K;
    float w = W[(size_t)k * N + n];
    __nv_bfloat16 h = __float2bfloat16(w);
    __nv_bfloat16 l = __float2bfloat16(w - __bfloat162float(h));
    __nv_bfloat16* row = Bt + (size_t)n * 3 * K;
    row[k]         = h;
    row[K + k]     = h;
    row[2 * K + k] = l;
}

// ---------------------------------------------------------------------------
// bf16 tensor-core GEMM: C[M][Nc] = A[M][Kp] @ Bt[Nc][Kp]^T
// 128 x BTN block tile, 8 warps (warp 32 x BTN/2), K-step 32,
// cp.async double-buffered.
// ---------------------------------------------------------------------------
__device__ __forceinline__ void cp16(void* dst_smem, const void* src) {
    uint32_t d = (uint32_t)__cvta_generic_to_shared(dst_smem);
    asm volatile("cp.async.cg.shared.global [%0], [%1], 16;" :: "r"(d), "l"(src));
}

__device__ __forceinline__ void mma_bf16(float c[4],
    uint32_t a0, uint32_t a1, uint32_t a2, uint32_t a3,
    uint32_t b0, uint32_t b1)
{
    asm volatile(
        "mma.sync.aligned.m16n8k16.row.col.f32.bf16.bf16.f32 "
        "{%0,%1,%2,%3}, {%4,%5,%6,%7}, {%8,%9}, {%0,%1,%2,%3};"
        : "+f"(c[0]), "+f"(c[1]), "+f"(c[2]), "+f"(c[3])
        : "r"(a0), "r"(a1), "r"(a2), "r"(a3), "r"(b0), "r"(b1));
}

template<int BTN>
__global__ __launch_bounds__(256) void bf16_gemm(
    const __nv_bfloat16* __restrict__ A, const __nv_bfloat16* __restrict__ Bt,
    float* __restrict__ C, int M, int Nc, int Kp)
{
    constexpr int P = 40;   // smem row pitch in bf16 (80B: 16B-aligned, conflict-free)
    __shared__ __nv_bfloat16 As[2][128 * P];
    __shared__ __nv_bfloat16 Bs[2][BTN * P];

    const int tid  = threadIdx.x;
    const int warp = tid >> 5;
    const int lane = tid & 31;
    const int l4 = lane >> 2;   // 0..7
    const int lm = lane & 3;    // 0..3
    const int warpM = warp & 3;
    const int warpN = warp >> 2;
    constexpr int WN = BTN / 2;
    constexpr int NT = WN / 8;
    const int m0 = warpM * 32;
    const int n0 = warpN * WN;
    const int rowBlock = blockIdx.y * 128;
    const int colBlock = blockIdx.x * BTN;

    float acc[2][NT][4];
    #pragma unroll
    for (int mt = 0; mt < 2; mt++)
        #pragma unroll
        for (int nt = 0; nt < NT; nt++)
            #pragma unroll
            for (int j = 0; j < 4; j++) acc[mt][nt][j] = 0.f;

    auto load_stage = [&](int s, int k0) {
        #pragma unroll
        for (int ch = tid; ch < 512; ch += 256) {          // A: 128 rows x 4 chunks
            int r = ch >> 2, c = ch & 3;
            cp16(&As[s][r * P + c * 8],
                 A + (size_t)(rowBlock + r) * Kp + k0 + c * 8);
        }
        #pragma unroll
        for (int ch = tid; ch < BTN * 4; ch += 256) {      // B: BTN rows x 4 chunks
            int r = ch >> 2, c = ch & 3;
            cp16(&Bs[s][r * P + c * 8],
                 Bt + (size_t)(colBlock + r) * Kp + k0 + c * 8);
        }
    };

    load_stage(0, 0);
    asm volatile("cp.async.commit_group;");
    load_stage(1, 32);
    asm volatile("cp.async.commit_group;");

    int s = 0;
    for (int k0 = 0; k0 < Kp; k0 += 32) {
        asm volatile("cp.async.wait_group 1;");
        __syncthreads();

        #pragma unroll
        for (int kk = 0; kk < 32; kk += 16) {
            uint32_t a[2][4];
            #pragma unroll
            for (int mt = 0; mt < 2; mt++) {
                const __nv_bfloat16* ap =
                    &As[s][(m0 + mt * 16 + l4) * P + kk + 2 * lm];
                a[mt][0] = *(const uint32_t*)(ap);
                a[mt][1] = *(const uint32_t*)(ap + 8 * P);
                a[mt][2] = *(const uint32_t*)(ap + 8);
                a[mt][3] = *(const uint32_t*)(ap + 8 * P + 8);
            }
            #pragma unroll
            for (int nt = 0; nt < NT; nt++) {
                const __nv_bfloat16* bp =
                    &Bs[s][(n0 + nt * 8 + l4) * P + kk + 2 * lm];
                uint32_t b0 = *(const uint32_t*)(bp);
                uint32_t b1 = *(const uint32_t*)(bp + 8);
                #pragma unroll
                for (int mt = 0; mt < 2; mt++)
                    mma_bf16(acc[mt][nt], a[mt][0], a[mt][1], a[mt][2], a[mt][3],
                             b0, b1);
            }
        }
        __syncthreads();
        if (k0 + 64 < Kp) load_stage(s, k0 + 64);
        asm volatile("cp.async.commit_group;");
        s ^= 1;
    }

    // epilogue
    #pragma unroll
    for (int mt = 0; mt < 2; mt++) {
        int r = rowBlock + m0 + mt * 16 + l4;
        #pragma unroll
        for (int nt = 0; nt < NT; nt++) {
            int c = colBlock + n0 + nt * 8 + lm * 2;
            if (r < M)
                *(float2*)(C + (size_t)r * Nc + c) =
                    make_float2(acc[mt][nt][0], acc[mt][nt][1]);
            if (r + 8 < M)
                *(float2*)(C + (size_t)(r + 8) * Nc + c) =
                    make_float2(acc[mt][nt][2], acc[mt][nt][3]);
        }
    }
}

// ---------------------------------------------------------------------------
// SPMM over NHID=256: warp per edge, red.global.add.v4.f32 scatter
// ---------------------------------------------------------------------------
__device__ __forceinline__ void red_add_v4(float4* ptr, float4 v) {
    asm volatile("red.global.add.v4.f32 [%0], {%1,%2,%3,%4};"
                 :: "l"(ptr), "f"(v.x), "f"(v.y), "f"(v.z), "f"(v.w)
                 : "memory");
}

__global__ __launch_bounds__(256) void spmm_nhid(
    const int* __restrict__ row, const int* __restrict__ col,
    const float* __restrict__ val)
{
    int e = blockIdx.x * (blockDim.x >> 5) + (threadIdx.x >> 5);
    if (e >= E_EDGES) return;
    int lane = threadIdx.x & 31;
    int c = col[e];
    int r = row[e];
    float v = val[e];
    const float4* s = (const float4*)(g_xw1 + (long)c * NHID);
    float4*       d = (float4*)(g_h   + (long)r * NHID);
    #pragma unroll
    for (int j = 0; j < 2; j++) {
        float4 x = s[lane + 32 * j];
        x.x *= v; x.y *= v; x.z *= v; x.w *= v;
        red_add_v4(d + lane + 32 * j, x);
    }
}

// ---------------------------------------------------------------------------
// SPMM over NCLASS=64: 16 threads per edge
// ---------------------------------------------------------------------------
__global__ __launch_bounds__(256) void spmm_ncls(
    const int* __restrict__ row, const int* __restrict__ col,
    const float* __restrict__ val)
{
    long t = (long)blockIdx.x * blockDim.x + threadIdx.x;
    int e = (int)(t >> 4);
    if (e >= E_EDGES) return;
    int l = (int)(t & 15);
    int c = col[e];
    int r = row[e];
    float v = val[e];
    const float4* s = (const float4*)(g_hw2 + (long)c * NCLASS);
    float4*       d = (float4*)(g_h2  + (long)r * NCLASS);
    float4 x = s[l];
    x.x *= v; x.y *= v; x.z *= v; x.w *= v;
    red_add_v4(d + l, x);
}

// ---------------------------------------------------------------------------
// Final: logits = (h2 + b2) @ LW + Lb ; log_softmax. One warp per node.
// ---------------------------------------------------------------------------
__global__ __launch_bounds__(256) void final_kernel(
    const float* __restrict__ b2, const float* __restrict__ LW,
    const float* __restrict__ Lb, float* __restrict__ out)
{
    __shared__ float sLW[NCLASS * NCLASS];
    __shared__ float sh2[8][NCLASS];
    const int tid = threadIdx.x;
    for (int i = tid; i < NCLASS * NCLASS; i += 256) sLW[i] = LW[i];

    const int warp = tid >> 5;
    const int lane = tid & 31;
    const int node = blockIdx.x * 8 + warp;

    if (node < N_NODES) {
        sh2[warp][lane]      = g_h2[(long)node * NCLASS + lane]      + b2[lane];
        sh2[warp][lane + 32] = g_h2[(long)node * NCLASS + lane + 32] + b2[lane + 32];
    }
    __syncthreads();
    if (node >= N_NODES) return;

    float l0 = Lb[lane];
    float l1 = Lb[lane + 32];
    #pragma unroll
    for (int k = 0; k < NCLASS; k++) {
        float hv = sh2[warp][k];
        l0 += hv * sLW[k * NCLASS + lane];
        l1 += hv * sLW[k * NCLASS + lane + 32];
    }

    float m = fmaxf(l0, l1);
    #pragma unroll
    for (int off = 16; off; off >>= 1)
        m = fmaxf(m, __shfl_xor_sync(0xffffffff, m, off));
    float s = expf(l0 - m) + expf(l1 - m);
    #pragma unroll
    for (int off = 16; off; off >>= 1)
        s += __shfl_xor_sync(0xffffffff, s, off);
    float lse = m + logf(s);

    out[(long)node * NCLASS + lane]      = l0 - lse;
    out[(long)node * NCLASS + lane + 32] = l1 - lse;
}

// ---------------------------------------------------------------------------
// Launch
// ---------------------------------------------------------------------------
extern "C" void kernel_launch(void* const* d_in, const int* in_sizes, int n_in,
                              void* d_out, int out_size)
{
    const float* x   = (const float*)d_in[0];
    const float* a0v = (const float*)d_in[1];
    const float* a1v = (const float*)d_in[2];
    const float* W1  = (const float*)d_in[3];
    const float* b1  = (const float*)d_in[4];
    const float* W2  = (const float*)d_in[5];
    const float* b2  = (const float*)d_in[6];
    const float* LW  = (const float*)d_in[7];
    const float* Lb  = (const float*)d_in[8];
    const int*   a0r = (const int*)d_in[9];
    const int*   a0c = (const int*)d_in[10];
    const int*   a1r = (const int*)d_in[11];
    const int*   a1c = (const int*)d_in[12];
    float* out = (float*)d_out;

    float *p_xw1, *p_h, *p_hw2;
    __nv_bfloat16 *p_A1, *p_B1, *p_A2, *p_B2;
    cudaGetSymbolAddress((void**)&p_xw1, g_xw1);
    cudaGetSymbolAddress((void**)&p_h,   g_h);
    cudaGetSymbolAddress((void**)&p_hw2, g_hw2);
    cudaGetSymbolAddress((void**)&p_A1,  g_A1);
    cudaGetSymbolAddress((void**)&p_B1,  g_B1);
    cudaGetSymbolAddress((void**)&p_A2,  g_A2);
    cudaGetSymbolAddress((void**)&p_B2,  g_B2);

    // Zero accumulators
    {
        int threads = N_NODES * NHID / 4;
        zero_kernel<<<(threads + 255) / 256, 256>>>();
    }

    // Split x -> g_A1 (bf16 hi/lo triple), W1 -> g_B1
    {
        long total = (long)M_PAD * (NFEAT / 4);
        conv_split<false><<<(int)((total + 255) / 256), 256>>>(x, nullptr, p_A1,
                                                               N_NODES, NFEAT);
        conv_w<<<(NFEAT * NHID + 255) / 256, 256>>>(W1, p_B1, NFEAT, NHID);
    }

    // GEMM1: g_xw1 = x @ W1 via bf16 3-term (Kp = 1536)
    {
        dim3 grid(NHID / 128, M_PAD / 128);
        bf16_gemm<128><<<grid, 256>>>(p_A1, p_B1, p_xw1, N_NODES, NHID, 3 * NFEAT);
    }

    // SPMM0: g_h += adj0 * g_xw1
    {
        int blocks = (E_EDGES + 7) / 8;
        spmm_nhid<<<blocks, 256>>>(a0r, a0c, a0v);
    }

    // Split relu(g_h + b1) -> g_A2, W2 -> g_B2
    {
        long total = (long)M_PAD * (NHID / 4);
        conv_split<true><<<(int)((total + 255) / 256), 256>>>(p_h, b1, p_A2,
                                                              N_NODES, NHID);
        conv_w<<<(NHID * NCLASS + 255) / 256, 256>>>(W2, p_B2, NHID, NCLASS);
    }

    // GEMM2: g_hw2 = relu(g_h+b1) @ W2 via bf16 3-term (Kp = 768)
    {
        dim3 grid(1, M_PAD / 128);
        bf16_gemm<64><<<grid, 256>>>(p_A2, p_B2, p_hw2, N_NODES, NCLASS, 3 * NHID);
    }

    // SPMM1: g_h2 += adj1 * g_hw2
    {
        long threads = (long)E_EDGES * 16;
        spmm_ncls<<<(int)((threads + 255) / 256), 256>>>(a1r, a1c, a1v);
    }

    // Final linear + log_softmax
    {
        final_kernel<<<(N_NODES + 7) / 8, 256>>>(b2, LW, Lb, out);
    }
}